// round 15
// baseline (speedup 1.0000x reference)
#include <cuda_runtime.h>
#include <cuda_fp16.h>
#include <cstdint>
#include <math.h>

#define D_MODEL 1024
#define NUM_HEADS 16
#define HEAD_DIM 64
#define BATCH 4
#define SEQ 2048
#define M_TOTAL (BATCH * SEQ)

// Scratch (allocation-free rule: device globals)
__device__ __half g_Xh[M_TOTAL * D_MODEL];                      // x, fp16
__device__ __half g_Qh[M_TOTAL * D_MODEL];                      // Q*log2e/32
__device__ __half g_Kh[M_TOTAL * D_MODEL];                      // fp16
__device__ __half g_Vh[M_TOTAL * D_MODEL];                      // V, normal layout
__device__ __half g_Wh[3 * D_MODEL * D_MODEL];                  // [z][n][k]

// ---------------------------------------------------------------------------
// MMA / LDSM / cp.async / math helpers
// ---------------------------------------------------------------------------
__device__ __forceinline__ void mma_16n8k16_f16(float* d, const uint32_t* a,
                                                uint32_t b0, uint32_t b1) {
    asm volatile(
        "mma.sync.aligned.m16n8k16.row.col.f32.f16.f16.f32 "
        "{%0,%1,%2,%3}, {%4,%5,%6,%7}, {%8,%9}, {%0,%1,%2,%3};"
        : "+f"(d[0]), "+f"(d[1]), "+f"(d[2]), "+f"(d[3])
        : "r"(a[0]), "r"(a[1]), "r"(a[2]), "r"(a[3]), "r"(b0), "r"(b1));
}

__device__ __forceinline__ void ldsm_x4(uint32_t& r0, uint32_t& r1,
                                        uint32_t& r2, uint32_t& r3,
                                        uint32_t saddr) {
    asm volatile("ldmatrix.sync.aligned.m8n8.x4.shared.b16 {%0,%1,%2,%3}, [%4];"
                 : "=r"(r0), "=r"(r1), "=r"(r2), "=r"(r3) : "r"(saddr));
}

// Transposed variant: loads B-fragments from [k][n] row-major storage.
__device__ __forceinline__ void ldsm_x4_t(uint32_t& r0, uint32_t& r1,
                                          uint32_t& r2, uint32_t& r3,
                                          uint32_t saddr) {
    asm volatile("ldmatrix.sync.aligned.m8n8.x4.trans.shared.b16 {%0,%1,%2,%3}, [%4];"
                 : "=r"(r0), "=r"(r1), "=r"(r2), "=r"(r3) : "r"(saddr));
}

__device__ __forceinline__ void cp16(uint32_t dst, const void* src) {
    asm volatile("cp.async.cg.shared.global [%0], [%1], 16;"
                 :: "r"(dst), "l"(src));
}
#define CP_COMMIT() asm volatile("cp.async.commit_group;")
#define CP_WAIT0()  asm volatile("cp.async.wait_group 0;")
#define CP_WAIT1()  asm volatile("cp.async.wait_group 1;")
#define CP_WAIT2()  asm volatile("cp.async.wait_group 2;")

__device__ __forceinline__ uint32_t pack_h2(float a, float b) {
    __half2 h = __floats2half2_rn(a, b);
    return *(uint32_t*)&h;
}

__device__ __forceinline__ uint32_t h2_exp2(uint32_t x) {
    uint32_t r;
    asm("ex2.approx.f16x2 %0, %1;" : "=r"(r) : "r"(x));
    return r;
}

#define H2_ONES 0x3C003C00u

// ---------------------------------------------------------------------------
// Converters
// ---------------------------------------------------------------------------
__global__ void convert_x(const float* __restrict__ x)
{
    const size_t i = ((size_t)blockIdx.x * 256 + threadIdx.x) * 8;
    float4 a = *(const float4*)(x + i);
    float4 c = *(const float4*)(x + i + 4);
    uint4 o;
    o.x = pack_h2(a.x, a.y); o.y = pack_h2(a.z, a.w);
    o.z = pack_h2(c.x, c.y); o.w = pack_h2(c.z, c.w);
    *(uint4*)&g_Xh[i] = o;
}

__global__ void convert_w(const float* __restrict__ Wq,
                          const float* __restrict__ Wk,
                          const float* __restrict__ Wv)
{
    __shared__ float tile[32][33];
    const float* src = (blockIdx.z == 0) ? Wq : (blockIdx.z == 1) ? Wk : Wv;
    __half* dst = g_Wh + (size_t)blockIdx.z * D_MODEL * D_MODEL;
    int n0 = blockIdx.x * 32, k0 = blockIdx.y * 32;
    int tx = threadIdx.x, ty0 = threadIdx.y;
#pragma unroll
    for (int i = 0; i < 4; i++) {
        int ty = ty0 + i * 8;
        tile[ty][tx] = src[(size_t)(k0 + ty) * D_MODEL + n0 + tx];
    }
    __syncthreads();
#pragma unroll
    for (int i = 0; i < 4; i++) {
        int ty = ty0 + i * 8;
        dst[(size_t)(n0 + ty) * D_MODEL + k0 + tx] = __float2half_rn(tile[tx][ty]);
    }
}

// ---------------------------------------------------------------------------
// fp16 GEMM, all three projections; cp.async 4-stage pipeline with wait2
// (proven R12 structure). Uniform coalesced epilogue for all z.
// ---------------------------------------------------------------------------
#define PAH 40
#define PBH 40
#define GSTG 4
#define ABYTES (128 * PAH * 2)
#define BBYTES (128 * PBH * 2)

__global__ __launch_bounds__(256, 2) void gemm_f16_all(
    const float* __restrict__ bq, const float* __restrict__ bk,
    const float* __restrict__ bv)
{
    __shared__ __half As[GSTG][128 * PAH];
    __shared__ __half Bs[GSTG][128 * PBH];

    const int t = threadIdx.x;
    const int wid = t >> 5;
    const int lane = t & 31;
    const int grp = lane >> 2;
    const int qid = lane & 3;
    const int z = blockIdx.z;

    const __half* Xh = g_Xh;
    const __half* Wz = g_Wh + (size_t)z * D_MODEL * D_MODEL;
    const float* bias = (z == 0) ? bq : (z == 1) ? bk : bv;
    const float out_scale = (z == 0) ? (0.03125f * 1.44269504f) : 1.0f;
    __half* C = (z == 0) ? g_Qh : (z == 1) ? g_Kh : g_Vh;

    const int warp_m = wid & 3;
    const int warp_n = wid >> 2;
    const int row0 = blockIdx.y * 128;
    const int col0 = blockIdx.x * 128;

    const int ar = t >> 1;
    const int ak = (t & 1) * 16;
    const __half* Ag = Xh + (size_t)(row0 + ar) * D_MODEL + ak;
    const __half* Bg = Wz + (size_t)(col0 + ar) * D_MODEL + ak;
    const uint32_t adst0 = (uint32_t)__cvta_generic_to_shared(&As[0][0]) +
                           (uint32_t)(ar * PAH + ak) * 2;
    const uint32_t bdst0 = (uint32_t)__cvta_generic_to_shared(&Bs[0][0]) +
                           (uint32_t)(ar * PBH + ak) * 2;

    const int a_row = (lane & 7) + ((lane >> 3) & 1) * 8;
    const int a_c8 = (lane >> 4) * 8;
    const uint32_t a_lane2 = (uint32_t)(a_row * PAH + a_c8) * 2;
    const int b_n = (lane & 7) + (lane >> 4) * 8;
    const int b_k8 = ((lane >> 3) & 1) * 8;
    const uint32_t b_lane2 = (uint32_t)(b_n * PBH + b_k8) * 2;

    const uint32_t as0 = (uint32_t)__cvta_generic_to_shared(&As[0][0]) + a_lane2;
    const uint32_t bs0 = (uint32_t)__cvta_generic_to_shared(&Bs[0][0]) + b_lane2;

    float acc[2][8][4];
#pragma unroll
    for (int i = 0; i < 2; i++)
#pragma unroll
        for (int j = 0; j < 8; j++)
#pragma unroll
            for (int k = 0; k < 4; k++) acc[i][j][k] = 0.f;

    // Prologue: stage chunks 0 and 1 (two groups)
#pragma unroll
    for (int pc = 0; pc < 2; pc++) {
        cp16(adst0 + pc * ABYTES, Ag + pc * 32);
        cp16(adst0 + pc * ABYTES + 16, Ag + pc * 32 + 8);
        cp16(bdst0 + pc * BBYTES, Bg + pc * 32);
        cp16(bdst0 + pc * BBYTES + 16, Bg + pc * 32 + 8);
        CP_COMMIT();
    }

    const int NCHUNK = D_MODEL / 32;  // 32
    for (int ic = 0; ic < NCHUNK; ic++) {
        if (ic + 2 < NCHUNK) {
            const int st = (ic + 2) & 3;
            const int kc = (ic + 2) * 32;
            cp16(adst0 + st * ABYTES, Ag + kc);
            cp16(adst0 + st * ABYTES + 16, Ag + kc + 8);
            cp16(bdst0 + st * BBYTES, Bg + kc);
            cp16(bdst0 + st * BBYTES + 16, Bg + kc + 8);
        }
        CP_COMMIT();   // unconditional: keeps group count aligned at the tail
        CP_WAIT2();    // chunk ic complete
        __syncthreads();

        const int st = ic & 3;
        const uint32_t asb = as0 + st * ABYTES;
        const uint32_t bsb = bs0 + st * BBYTES;
#pragma unroll
        for (int ks = 0; ks < 2; ks++) {
            const int k0 = ks * 16;
            uint32_t afr[2][4];
            ldsm_x4(afr[0][0], afr[0][1], afr[0][2], afr[0][3],
                    asb + (uint32_t)((warp_m * 32) * PAH + k0) * 2);
            ldsm_x4(afr[1][0], afr[1][1], afr[1][2], afr[1][3],
                    asb + (uint32_t)((warp_m * 32 + 16) * PAH + k0) * 2);
            uint32_t bfr[8][2];
#pragma unroll
            for (int j = 0; j < 4; j++) {
                uint32_t r0, r1, r2, r3;
                ldsm_x4(r0, r1, r2, r3,
                        bsb + (uint32_t)((warp_n * 64 + 16 * j) * PBH + k0) * 2);
                bfr[2 * j][0] = r0;     bfr[2 * j][1] = r1;
                bfr[2 * j + 1][0] = r2; bfr[2 * j + 1][1] = r3;
            }
#pragma unroll
            for (int nt = 0; nt < 8; nt++) {
                mma_16n8k16_f16(acc[0][nt], afr[0], bfr[nt][0], bfr[nt][1]);
                mma_16n8k16_f16(acc[1][nt], afr[1], bfr[nt][0], bfr[nt][1]);
            }
        }
    }

    // Epilogue (uniform, coalesced for all z)
#pragma unroll
    for (int mt = 0; mt < 2; mt++) {
        const int r_lo = row0 + warp_m * 32 + mt * 16 + grp;
#pragma unroll
        for (int nt = 0; nt < 8; nt++) {
            const int col = col0 + warp_n * 64 + nt * 8 + 2 * qid;
            float2 bb = *(const float2*)&bias[col];
            float v00 = (acc[mt][nt][0] + bb.x) * out_scale;
            float v01 = (acc[mt][nt][1] + bb.y) * out_scale;
            float v10 = (acc[mt][nt][2] + bb.x) * out_scale;
            float v11 = (acc[mt][nt][3] + bb.y) * out_scale;
            *(uint32_t*)&C[(size_t)r_lo * D_MODEL + col] = pack_h2(v00, v01);
            *(uint32_t*)&C[(size_t)(r_lo + 8) * D_MODEL + col] = pack_h2(v10, v11);
        }
    }
}

// ---------------------------------------------------------------------------
// fp16 flash attention v6: 128-thread CTA (4 warps x 32 Q rows = 128 rows),
// 2 CTAs/SM for finer wave-tail granularity. 2-buffer cp.async staging,
// V in normal layout via ldmatrix.trans, max-free exp2 softmax.
// ---------------------------------------------------------------------------
#define PKH 72
#define KVBUF (64 * PKH)
#define BUFB (KVBUF * 2)   // bytes per buffer

__global__ __launch_bounds__(128, 2) void attn_f16(float* __restrict__ O)
{
    __shared__ __half Ksh[2][KVBUF];
    __shared__ __half Vsh[2][KVBUF];

    const int t = threadIdx.x;
    const int lane = t & 31;
    const int w = t >> 5;          // 0..3
    const int grp = lane >> 2;
    const int qid = lane & 3;

    const int bh = blockIdx.y;
    const int b = bh >> 4;
    const int h = bh & 15;
    const int q0 = blockIdx.x * 128;

    const __half* Qb = g_Qh + (size_t)b * SEQ * D_MODEL + h * HEAD_DIM;
    const __half* Kb = g_Kh + (size_t)b * SEQ * D_MODEL + h * HEAD_DIM;
    const __half* Vb = g_Vh + (size_t)b * SEQ * D_MODEL + h * HEAD_DIM;
    float* Ob = O + (size_t)b * SEQ * D_MODEL + h * HEAD_DIM;

    const int mb = w * 32;

    uint32_t aQ[2][4][4];
#pragma unroll
    for (int mt = 0; mt < 2; mt++) {
        const __half* qr0 = Qb + (size_t)(q0 + mb + mt * 16 + grp) * D_MODEL;
        const __half* qr1 = qr0 + 8 * D_MODEL;
#pragma unroll
        for (int ks = 0; ks < 4; ks++) {
            const int c = ks * 16 + 2 * qid;
            aQ[mt][ks][0] = *(const uint32_t*)&qr0[c];
            aQ[mt][ks][1] = *(const uint32_t*)&qr1[c];
            aQ[mt][ks][2] = *(const uint32_t*)&qr0[c + 8];
            aQ[mt][ks][3] = *(const uint32_t*)&qr1[c + 8];
        }
    }

    // K fragment lane offset (B pattern from [n=kv][k=d], pitch PKH)
    const int b_n = (lane & 7) + (lane >> 4) * 8;
    const int b_k8 = ((lane >> 3) & 1) * 8;
    const uint32_t k_lane2 = (uint32_t)(b_n * PKH + b_k8) * 2;
    // V fragment lane offset (trans pattern from [k=kv][n=d], pitch PKH)
    const uint32_t v_lane2 = (uint32_t)((lane & 15) * PKH + (lane >> 4) * 8) * 2;

    const uint32_t ks_s0 = (uint32_t)__cvta_generic_to_shared(&Ksh[0][0]) + k_lane2;
    const uint32_t vs_s0 = (uint32_t)__cvta_generic_to_shared(&Vsh[0][0]) + v_lane2;

    // cp.async staging with 128 threads: thread loads 64B of K and 64B of V
    // per tile: row kvr (0..63), cols [kvc, kvc+32)
    const int kvr = t >> 1;
    const int kvc = (t & 1) * 32;
    const __half* kg = Kb + (size_t)kvr * D_MODEL + kvc;
    const __half* vg = Vb + (size_t)kvr * D_MODEL + kvc;
    const uint32_t kdst = (uint32_t)__cvta_generic_to_shared(&Ksh[0][0]) +
                          (uint32_t)(kvr * PKH + kvc) * 2;
    const uint32_t vdst = (uint32_t)__cvta_generic_to_shared(&Vsh[0][0]) +
                          (uint32_t)(kvr * PKH + kvc) * 2;

    float oacc[2][8][4];
#pragma unroll
    for (int m = 0; m < 2; m++)
#pragma unroll
        for (int i = 0; i < 8; i++)
#pragma unroll
            for (int j = 0; j < 4; j++) oacc[m][i][j] = 0.f;
    float lacc[2][4] = {{0.f, 0.f, 0.f, 0.f}, {0.f, 0.f, 0.f, 0.f}};

    // Prologue: stage tile 0 into buffer 0
#pragma unroll
    for (int i = 0; i < 4; i++) {
        cp16(kdst + i * 16, kg + i * 8);
        cp16(vdst + i * 16, vg + i * 8);
    }
    CP_COMMIT();

    const int NT = SEQ / 64;
    for (int kt = 0; kt < NT; kt++) {
        const int cb = kt & 1;
        if (kt + 1 < NT) {
            const uint32_t off = (1 - cb) * BUFB;
            const size_t go = (size_t)(kt + 1) * 64 * D_MODEL;
#pragma unroll
            for (int i = 0; i < 4; i++) {
                cp16(kdst + off + i * 16, kg + go + i * 8);
                cp16(vdst + off + i * 16, vg + go + i * 8);
            }
            CP_COMMIT();
            CP_WAIT1();
        } else {
            CP_WAIT0();
        }
        __syncthreads();

        const uint32_t ksb = ks_s0 + cb * BUFB;
        const uint32_t vsb = vs_s0 + cb * BUFB;

#pragma unroll
        for (int j = 0; j < 4; j++) {
            // ---- S_log2 for kv cols [16j, 16j+16) ----
            float sacc[2][2][4];
#pragma unroll
            for (int m = 0; m < 2; m++)
#pragma unroll
                for (int s = 0; s < 2; s++)
#pragma unroll
                    for (int c = 0; c < 4; c++) sacc[m][s][c] = 0.f;

#pragma unroll
            for (int ks = 0; ks < 4; ks++) {
                const int k0 = ks * 16;
                uint32_t r0, r1, r2, r3;
                ldsm_x4(r0, r1, r2, r3,
                        ksb + (uint32_t)((16 * j) * PKH + k0) * 2);
                mma_16n8k16_f16(sacc[0][0], aQ[0][ks], r0, r1);
                mma_16n8k16_f16(sacc[0][1], aQ[0][ks], r2, r3);
                mma_16n8k16_f16(sacc[1][0], aQ[1][ks], r0, r1);
                mma_16n8k16_f16(sacc[1][1], aQ[1][ks], r2, r3);
            }

            // ---- P = 2^S, l += P @ ones ----
            uint32_t pf[2][4];
#pragma unroll
            for (int m = 0; m < 2; m++) {
                pf[m][0] = h2_exp2(pack_h2(sacc[m][0][0], sacc[m][0][1]));
                pf[m][1] = h2_exp2(pack_h2(sacc[m][0][2], sacc[m][0][3]));
                pf[m][2] = h2_exp2(pack_h2(sacc[m][1][0], sacc[m][1][1]));
                pf[m][3] = h2_exp2(pack_h2(sacc[m][1][2], sacc[m][1][3]));
                mma_16n8k16_f16(lacc[m], pf[m], H2_ONES, H2_ONES);
            }

            // ---- O += P_slice @ V_slice (V from [kv][d] via trans) ----
#pragma unroll
            for (int dj = 0; dj < 4; dj++) {
                uint32_t r0, r1, r2, r3;
                ldsm_x4_t(r0, r1, r2, r3,
                          vsb + (uint32_t)((j * 16) * PKH + dj * 16) * 2);
                mma_16n8k16_f16(oacc[0][2 * dj], pf[0], r0, r1);
                mma_16n8k16_f16(oacc[0][2 * dj + 1], pf[0], r2, r3);
                mma_16n8k16_f16(oacc[1][2 * dj], pf[1], r0, r1);
                mma_16n8k16_f16(oacc[1][2 * dj + 1], pf[1], r2, r3);
            }
        }
        __syncthreads();
    }

    // Epilogue
#pragma unroll
    for (int mt = 0; mt < 2; mt++) {
        const float inv0 = 1.0f / lacc[mt][0];
        const float inv1 = 1.0f / lacc[mt][2];
        const int row0 = q0 + mb + mt * 16 + grp;
#pragma unroll
        for (int nt = 0; nt < 8; nt++) {
            const int col = nt * 8 + 2 * qid;
            float2 o0 = {oacc[mt][nt][0] * inv0, oacc[mt][nt][1] * inv0};
            float2 o1 = {oacc[mt][nt][2] * inv1, oacc[mt][nt][3] * inv1};
            *(float2*)&Ob[(size_t)row0 * D_MODEL + col] = o0;
            *(float2*)&Ob[(size_t)(row0 + 8) * D_MODEL + col] = o1;
        }
    }
}

// ---------------------------------------------------------------------------
extern "C" void kernel_launch(void* const* d_in, const int* in_sizes, int n_in,
                              void* d_out, int out_size)
{
    const float* x  = (const float*)d_in[0];
    const float* Wq = (const float*)d_in[1];
    const float* bq = (const float*)d_in[2];
    const float* Wk = (const float*)d_in[3];
    const float* bk = (const float*)d_in[4];
    const float* Wv = (const float*)d_in[5];
    const float* bv = (const float*)d_in[6];
    float* out = (float*)d_out;

    convert_x<<<M_TOTAL * D_MODEL / (256 * 8), 256>>>(x);
    convert_w<<<dim3(32, 32, 3), dim3(32, 8)>>>(Wq, Wk, Wv);

    dim3 ggrid(D_MODEL / 128, M_TOTAL / 128, 3);  // (8, 64, 3)
    gemm_f16_all<<<ggrid, 256>>>(bq, bk, bv);

    dim3 agrid(SEQ / 128, BATCH * NUM_HEADS);  // (16, 64)
    attn_f16<<<agrid, 128>>>(out);
}

// round 17
// speedup vs baseline: 1.6065x; 1.6065x over previous
#include <cuda_runtime.h>
#include <cuda_fp16.h>
#include <cstdint>
#include <math.h>

#define D_MODEL 1024
#define NUM_HEADS 16
#define HEAD_DIM 64
#define BATCH 4
#define SEQ 2048
#define M_TOTAL (BATCH * SEQ)

// Scratch (allocation-free rule: device globals)
__device__ __half g_Xh[M_TOTAL * D_MODEL];                      // x, fp16
__device__ __half g_Qh[M_TOTAL * D_MODEL];                      // Q*log2e/32
__device__ __half g_Kh[M_TOTAL * D_MODEL];                      // fp16
__device__ __half g_Vh[M_TOTAL * D_MODEL];                      // V, normal layout
__device__ __half g_Wh[3 * D_MODEL * D_MODEL];                  // [z][n][k]

// ---------------------------------------------------------------------------
// MMA / LDSM / cp.async / math helpers
// ---------------------------------------------------------------------------
__device__ __forceinline__ void mma_16n8k16_f16(float* d, const uint32_t* a,
                                                uint32_t b0, uint32_t b1) {
    asm volatile(
        "mma.sync.aligned.m16n8k16.row.col.f32.f16.f16.f32 "
        "{%0,%1,%2,%3}, {%4,%5,%6,%7}, {%8,%9}, {%0,%1,%2,%3};"
        : "+f"(d[0]), "+f"(d[1]), "+f"(d[2]), "+f"(d[3])
        : "r"(a[0]), "r"(a[1]), "r"(a[2]), "r"(a[3]), "r"(b0), "r"(b1));
}

__device__ __forceinline__ void ldsm_x4(uint32_t& r0, uint32_t& r1,
                                        uint32_t& r2, uint32_t& r3,
                                        uint32_t saddr) {
    asm volatile("ldmatrix.sync.aligned.m8n8.x4.shared.b16 {%0,%1,%2,%3}, [%4];"
                 : "=r"(r0), "=r"(r1), "=r"(r2), "=r"(r3) : "r"(saddr));
}

// Transposed variant: loads B-fragments from [k][n] row-major storage.
__device__ __forceinline__ void ldsm_x4_t(uint32_t& r0, uint32_t& r1,
                                          uint32_t& r2, uint32_t& r3,
                                          uint32_t saddr) {
    asm volatile("ldmatrix.sync.aligned.m8n8.x4.trans.shared.b16 {%0,%1,%2,%3}, [%4];"
                 : "=r"(r0), "=r"(r1), "=r"(r2), "=r"(r3) : "r"(saddr));
}

__device__ __forceinline__ void cp16(uint32_t dst, const void* src) {
    asm volatile("cp.async.cg.shared.global [%0], [%1], 16;"
                 :: "r"(dst), "l"(src));
}
#define CP_COMMIT() asm volatile("cp.async.commit_group;")
#define CP_WAIT0()  asm volatile("cp.async.wait_group 0;")
#define CP_WAIT1()  asm volatile("cp.async.wait_group 1;")
#define CP_WAIT2()  asm volatile("cp.async.wait_group 2;")

__device__ __forceinline__ uint32_t pack_h2(float a, float b) {
    __half2 h = __floats2half2_rn(a, b);
    return *(uint32_t*)&h;
}

__device__ __forceinline__ uint32_t h2_exp2(uint32_t x) {
    uint32_t r;
    asm("ex2.approx.f16x2 %0, %1;" : "=r"(r) : "r"(x));
    return r;
}

#define H2_ONES 0x3C003C00u

// ---------------------------------------------------------------------------
// Converters
// ---------------------------------------------------------------------------
__global__ void convert_x(const float* __restrict__ x)
{
    const size_t i = ((size_t)blockIdx.x * 256 + threadIdx.x) * 8;
    float4 a = *(const float4*)(x + i);
    float4 c = *(const float4*)(x + i + 4);
    uint4 o;
    o.x = pack_h2(a.x, a.y); o.y = pack_h2(a.z, a.w);
    o.z = pack_h2(c.x, c.y); o.w = pack_h2(c.z, c.w);
    *(uint4*)&g_Xh[i] = o;
}

__global__ void convert_w(const float* __restrict__ Wq,
                          const float* __restrict__ Wk,
                          const float* __restrict__ Wv)
{
    __shared__ float tile[32][33];
    const float* src = (blockIdx.z == 0) ? Wq : (blockIdx.z == 1) ? Wk : Wv;
    __half* dst = g_Wh + (size_t)blockIdx.z * D_MODEL * D_MODEL;
    int n0 = blockIdx.x * 32, k0 = blockIdx.y * 32;
    int tx = threadIdx.x, ty0 = threadIdx.y;
#pragma unroll
    for (int i = 0; i < 4; i++) {
        int ty = ty0 + i * 8;
        tile[ty][tx] = src[(size_t)(k0 + ty) * D_MODEL + n0 + tx];
    }
    __syncthreads();
#pragma unroll
    for (int i = 0; i < 4; i++) {
        int ty = ty0 + i * 8;
        dst[(size_t)(n0 + ty) * D_MODEL + k0 + tx] = __float2half_rn(tile[tx][ty]);
    }
}

// ---------------------------------------------------------------------------
// fp16 GEMM, all three projections; cp.async 4-stage wait2 pipeline (proven
// R12 structure). Uniform coalesced epilogue for all z (V in normal layout).
// ---------------------------------------------------------------------------
#define PAH 40
#define PBH 40
#define GSTG 4
#define ABYTES (128 * PAH * 2)
#define BBYTES (128 * PBH * 2)

__global__ __launch_bounds__(256, 2) void gemm_f16_all(
    const float* __restrict__ bq, const float* __restrict__ bk,
    const float* __restrict__ bv)
{
    __shared__ __half As[GSTG][128 * PAH];
    __shared__ __half Bs[GSTG][128 * PBH];

    const int t = threadIdx.x;
    const int wid = t >> 5;
    const int lane = t & 31;
    const int grp = lane >> 2;
    const int qid = lane & 3;
    const int z = blockIdx.z;

    const __half* Xh = g_Xh;
    const __half* Wz = g_Wh + (size_t)z * D_MODEL * D_MODEL;
    const float* bias = (z == 0) ? bq : (z == 1) ? bk : bv;
    const float out_scale = (z == 0) ? (0.03125f * 1.44269504f) : 1.0f;
    __half* C = (z == 0) ? g_Qh : (z == 1) ? g_Kh : g_Vh;

    const int warp_m = wid & 3;
    const int warp_n = wid >> 2;
    const int row0 = blockIdx.y * 128;
    const int col0 = blockIdx.x * 128;

    const int ar = t >> 1;
    const int ak = (t & 1) * 16;
    const __half* Ag = Xh + (size_t)(row0 + ar) * D_MODEL + ak;
    const __half* Bg = Wz + (size_t)(col0 + ar) * D_MODEL + ak;
    const uint32_t adst0 = (uint32_t)__cvta_generic_to_shared(&As[0][0]) +
                           (uint32_t)(ar * PAH + ak) * 2;
    const uint32_t bdst0 = (uint32_t)__cvta_generic_to_shared(&Bs[0][0]) +
                           (uint32_t)(ar * PBH + ak) * 2;

    const int a_row = (lane & 7) + ((lane >> 3) & 1) * 8;
    const int a_c8 = (lane >> 4) * 8;
    const uint32_t a_lane2 = (uint32_t)(a_row * PAH + a_c8) * 2;
    const int b_n = (lane & 7) + (lane >> 4) * 8;
    const int b_k8 = ((lane >> 3) & 1) * 8;
    const uint32_t b_lane2 = (uint32_t)(b_n * PBH + b_k8) * 2;

    const uint32_t as0 = (uint32_t)__cvta_generic_to_shared(&As[0][0]) + a_lane2;
    const uint32_t bs0 = (uint32_t)__cvta_generic_to_shared(&Bs[0][0]) + b_lane2;

    float acc[2][8][4];
#pragma unroll
    for (int i = 0; i < 2; i++)
#pragma unroll
        for (int j = 0; j < 8; j++)
#pragma unroll
            for (int k = 0; k < 4; k++) acc[i][j][k] = 0.f;

    // Prologue: stage chunks 0 and 1 (two groups)
#pragma unroll
    for (int pc = 0; pc < 2; pc++) {
        cp16(adst0 + pc * ABYTES, Ag + pc * 32);
        cp16(adst0 + pc * ABYTES + 16, Ag + pc * 32 + 8);
        cp16(bdst0 + pc * BBYTES, Bg + pc * 32);
        cp16(bdst0 + pc * BBYTES + 16, Bg + pc * 32 + 8);
        CP_COMMIT();
    }

    const int NCHUNK = D_MODEL / 32;  // 32
    for (int ic = 0; ic < NCHUNK; ic++) {
        if (ic + 2 < NCHUNK) {
            const int st = (ic + 2) & 3;
            const int kc = (ic + 2) * 32;
            cp16(adst0 + st * ABYTES, Ag + kc);
            cp16(adst0 + st * ABYTES + 16, Ag + kc + 8);
            cp16(bdst0 + st * BBYTES, Bg + kc);
            cp16(bdst0 + st * BBYTES + 16, Bg + kc + 8);
        }
        CP_COMMIT();   // unconditional: keeps group count aligned at the tail
        CP_WAIT2();    // chunk ic complete
        __syncthreads();

        const int st = ic & 3;
        const uint32_t asb = as0 + st * ABYTES;
        const uint32_t bsb = bs0 + st * BBYTES;
#pragma unroll
        for (int ks = 0; ks < 2; ks++) {
            const int k0 = ks * 16;
            uint32_t afr[2][4];
            ldsm_x4(afr[0][0], afr[0][1], afr[0][2], afr[0][3],
                    asb + (uint32_t)((warp_m * 32) * PAH + k0) * 2);
            ldsm_x4(afr[1][0], afr[1][1], afr[1][2], afr[1][3],
                    asb + (uint32_t)((warp_m * 32 + 16) * PAH + k0) * 2);
            uint32_t bfr[8][2];
#pragma unroll
            for (int j = 0; j < 4; j++) {
                uint32_t r0, r1, r2, r3;
                ldsm_x4(r0, r1, r2, r3,
                        bsb + (uint32_t)((warp_n * 64 + 16 * j) * PBH + k0) * 2);
                bfr[2 * j][0] = r0;     bfr[2 * j][1] = r1;
                bfr[2 * j + 1][0] = r2; bfr[2 * j + 1][1] = r3;
            }
#pragma unroll
            for (int nt = 0; nt < 8; nt++) {
                mma_16n8k16_f16(acc[0][nt], afr[0], bfr[nt][0], bfr[nt][1]);
                mma_16n8k16_f16(acc[1][nt], afr[1], bfr[nt][0], bfr[nt][1]);
            }
        }
    }

    // Epilogue (uniform, coalesced for all z)
#pragma unroll
    for (int mt = 0; mt < 2; mt++) {
        const int r_lo = row0 + warp_m * 32 + mt * 16 + grp;
#pragma unroll
        for (int nt = 0; nt < 8; nt++) {
            const int col = col0 + warp_n * 64 + nt * 8 + 2 * qid;
            float2 bb = *(const float2*)&bias[col];
            float v00 = (acc[mt][nt][0] + bb.x) * out_scale;
            float v01 = (acc[mt][nt][1] + bb.y) * out_scale;
            float v10 = (acc[mt][nt][2] + bb.x) * out_scale;
            float v11 = (acc[mt][nt][3] + bb.y) * out_scale;
            *(uint32_t*)&C[(size_t)r_lo * D_MODEL + col] = pack_h2(v00, v01);
            *(uint32_t*)&C[(size_t)(r_lo + 8) * D_MODEL + col] = pack_h2(v10, v11);
        }
    }
}

// ---------------------------------------------------------------------------
// fp16 flash attention (R13 structure, proven 199-200us): 256 threads,
// 8 warps x 32 Q rows (CTA = 256 Q rows), 2-buffer cp.async staging,
// max-free exp2 softmax. V in normal layout via ldmatrix.trans (R14-proven).
// ---------------------------------------------------------------------------
#define PKH 72
#define KVBUF (64 * PKH)
#define BUFB (KVBUF * 2)   // bytes per buffer

__global__ __launch_bounds__(256, 1) void attn_f16(float* __restrict__ O)
{
    __shared__ __half Ksh[2][KVBUF];
    __shared__ __half Vsh[2][KVBUF];

    const int t = threadIdx.x;
    const int lane = t & 31;
    const int w = t >> 5;
    const int grp = lane >> 2;
    const int qid = lane & 3;

    const int bh = blockIdx.y;
    const int b = bh >> 4;
    const int h = bh & 15;
    const int q0 = blockIdx.x * 256;

    const __half* Qb = g_Qh + (size_t)b * SEQ * D_MODEL + h * HEAD_DIM;
    const __half* Kb = g_Kh + (size_t)b * SEQ * D_MODEL + h * HEAD_DIM;
    const __half* Vb = g_Vh + (size_t)b * SEQ * D_MODEL + h * HEAD_DIM;
    float* Ob = O + (size_t)b * SEQ * D_MODEL + h * HEAD_DIM;

    const int mb = w * 32;

    uint32_t aQ[2][4][4];
#pragma unroll
    for (int mt = 0; mt < 2; mt++) {
        const __half* qr0 = Qb + (size_t)(q0 + mb + mt * 16 + grp) * D_MODEL;
        const __half* qr1 = qr0 + 8 * D_MODEL;
#pragma unroll
        for (int ks = 0; ks < 4; ks++) {
            const int c = ks * 16 + 2 * qid;
            aQ[mt][ks][0] = *(const uint32_t*)&qr0[c];
            aQ[mt][ks][1] = *(const uint32_t*)&qr1[c];
            aQ[mt][ks][2] = *(const uint32_t*)&qr0[c + 8];
            aQ[mt][ks][3] = *(const uint32_t*)&qr1[c + 8];
        }
    }

    // K fragment lane offset (B pattern from [n=kv][k=d], pitch PKH)
    const int b_n = (lane & 7) + (lane >> 4) * 8;
    const int b_k8 = ((lane >> 3) & 1) * 8;
    const uint32_t k_lane2 = (uint32_t)(b_n * PKH + b_k8) * 2;
    // V fragment lane offset (trans pattern from [k=kv][n=d], pitch PKH)
    const uint32_t v_lane2 = (uint32_t)((lane & 15) * PKH + (lane >> 4) * 8) * 2;

    const uint32_t ks_s0 = (uint32_t)__cvta_generic_to_shared(&Ksh[0][0]) + k_lane2;
    const uint32_t vs_s0 = (uint32_t)__cvta_generic_to_shared(&Vsh[0][0]) + v_lane2;

    // cp.async staging: thread loads 32B of K and 32B of V per tile
    const int kvr = t >> 2;
    const int kvc = (t & 3) * 16;
    const __half* kg = Kb + (size_t)kvr * D_MODEL + kvc;
    const __half* vg = Vb + (size_t)kvr * D_MODEL + kvc;
    const uint32_t kdst = (uint32_t)__cvta_generic_to_shared(&Ksh[0][0]) +
                          (uint32_t)(kvr * PKH + kvc) * 2;
    const uint32_t vdst = (uint32_t)__cvta_generic_to_shared(&Vsh[0][0]) +
                          (uint32_t)(kvr * PKH + kvc) * 2;

    float oacc[2][8][4];
#pragma unroll
    for (int m = 0; m < 2; m++)
#pragma unroll
        for (int i = 0; i < 8; i++)
#pragma unroll
            for (int j = 0; j < 4; j++) oacc[m][i][j] = 0.f;
    float lacc[2][4] = {{0.f, 0.f, 0.f, 0.f}, {0.f, 0.f, 0.f, 0.f}};

    // Prologue: stage tile 0 into buffer 0
    cp16(kdst, kg);
    cp16(kdst + 16, kg + 8);
    cp16(vdst, vg);
    cp16(vdst + 16, vg + 8);
    CP_COMMIT();

    const int NT = SEQ / 64;
    for (int kt = 0; kt < NT; kt++) {
        const int cb = kt & 1;
        if (kt + 1 < NT) {
            const uint32_t off = (1 - cb) * BUFB;
            const size_t go = (size_t)(kt + 1) * 64 * D_MODEL;
            cp16(kdst + off, kg + go);
            cp16(kdst + off + 16, kg + go + 8);
            cp16(vdst + off, vg + go);
            cp16(vdst + off + 16, vg + go + 8);
            CP_COMMIT();
            CP_WAIT1();
        } else {
            CP_WAIT0();
        }
        __syncthreads();

        const uint32_t ksb = ks_s0 + cb * BUFB;
        const uint32_t vsb = vs_s0 + cb * BUFB;

#pragma unroll
        for (int j = 0; j < 4; j++) {
            // ---- S_log2 for kv cols [16j, 16j+16) ----
            float sacc[2][2][4];
#pragma unroll
            for (int m = 0; m < 2; m++)
#pragma unroll
                for (int s = 0; s < 2; s++)
#pragma unroll
                    for (int c = 0; c < 4; c++) sacc[m][s][c] = 0.f;

#pragma unroll
            for (int ks = 0; ks < 4; ks++) {
                const int k0 = ks * 16;
                uint32_t r0, r1, r2, r3;
                ldsm_x4(r0, r1, r2, r3,
                        ksb + (uint32_t)((16 * j) * PKH + k0) * 2);
                mma_16n8k16_f16(sacc[0][0], aQ[0][ks], r0, r1);
                mma_16n8k16_f16(sacc[0][1], aQ[0][ks], r2, r3);
                mma_16n8k16_f16(sacc[1][0], aQ[1][ks], r0, r1);
                mma_16n8k16_f16(sacc[1][1], aQ[1][ks], r2, r3);
            }

            // ---- P = 2^S, l += P @ ones ----
            uint32_t pf[2][4];
#pragma unroll
            for (int m = 0; m < 2; m++) {
                pf[m][0] = h2_exp2(pack_h2(sacc[m][0][0], sacc[m][0][1]));
                pf[m][1] = h2_exp2(pack_h2(sacc[m][0][2], sacc[m][0][3]));
                pf[m][2] = h2_exp2(pack_h2(sacc[m][1][0], sacc[m][1][1]));
                pf[m][3] = h2_exp2(pack_h2(sacc[m][1][2], sacc[m][1][3]));
                mma_16n8k16_f16(lacc[m], pf[m], H2_ONES, H2_ONES);
            }

            // ---- O += P_slice @ V_slice (V from [kv][d] via trans) ----
#pragma unroll
            for (int dj = 0; dj < 4; dj++) {
                uint32_t r0, r1, r2, r3;
                ldsm_x4_t(r0, r1, r2, r3,
                          vsb + (uint32_t)((j * 16) * PKH + dj * 16) * 2);
                mma_16n8k16_f16(oacc[0][2 * dj], pf[0], r0, r1);
                mma_16n8k16_f16(oacc[0][2 * dj + 1], pf[0], r2, r3);
                mma_16n8k16_f16(oacc[1][2 * dj], pf[1], r0, r1);
                mma_16n8k16_f16(oacc[1][2 * dj + 1], pf[1], r2, r3);
            }
        }
        __syncthreads();
    }

    // Epilogue
#pragma unroll
    for (int mt = 0; mt < 2; mt++) {
        const float inv0 = 1.0f / lacc[mt][0];
        const float inv1 = 1.0f / lacc[mt][2];
        const int row0 = q0 + mb + mt * 16 + grp;
#pragma unroll
        for (int nt = 0; nt < 8; nt++) {
            const int col = nt * 8 + 2 * qid;
            float2 o0 = {oacc[mt][nt][0] * inv0, oacc[mt][nt][1] * inv0};
            float2 o1 = {oacc[mt][nt][2] * inv1, oacc[mt][nt][3] * inv1};
            *(float2*)&Ob[(size_t)row0 * D_MODEL + col] = o0;
            *(float2*)&Ob[(size_t)(row0 + 8) * D_MODEL + col] = o1;
        }
    }
}

// ---------------------------------------------------------------------------
extern "C" void kernel_launch(void* const* d_in, const int* in_sizes, int n_in,
                              void* d_out, int out_size)
{
    const float* x  = (const float*)d_in[0];
    const float* Wq = (const float*)d_in[1];
    const float* bq = (const float*)d_in[2];
    const float* Wk = (const float*)d_in[3];
    const float* bk = (const float*)d_in[4];
    const float* Wv = (const float*)d_in[5];
    const float* bv = (const float*)d_in[6];
    float* out = (float*)d_out;

    convert_x<<<M_TOTAL * D_MODEL / (256 * 8), 256>>>(x);
    convert_w<<<dim3(32, 32, 3), dim3(32, 8)>>>(Wq, Wk, Wv);

    dim3 ggrid(D_MODEL / 128, M_TOTAL / 128, 3);  // (8, 64, 3)
    gemm_f16_all<<<ggrid, 256>>>(bq, bk, bv);

    dim3 agrid(SEQ / 256, BATCH * NUM_HEADS);  // (8, 64)
    attn_f16<<<agrid, 256>>>(out);
}